// round 2
// baseline (speedup 1.0000x reference)
#include <cuda_runtime.h>
#include <stdint.h>
#include <math.h>

// DCGRU cell. N=4096 nodes, B=32 batch, IN_DIM=2, U=64, K=2 Chebyshev,
// 2 supports -> M=5 matrices, F=66 features, C=F*B=2112 SpMM width.
// Strategy: supports are ~1% sparse -> on-device CSR + smem-tiled SpMM (fp32),
// then dense (B*N,330)@(330,out) GEMMs with packed f32x2 FMA and fused epilogues.

#define NV 4096
#define BV 32
#define FV 66
#define CV (FV*BV)        // 2112
#define UV 64
#define NNZ_CAP 300000
#define TW 8              // SpMM column-tile width
#define NT (CV/TW)        // 264 tiles

typedef unsigned long long ull;

// ---------------- device scratch (no runtime allocation allowed) ----------------
__device__ float g_X1[(size_t)NV*CV];   // x0 for gconv1 (= mat m0)
__device__ float g_X2[(size_t)NV*CV];   // x0 for gconv2 (inputs + r*hx)
__device__ float g_M1[(size_t)NV*CV];   // S0 @ x0
__device__ float g_M2[(size_t)NV*CV];   // 2*S0@(S0@x0) - x0
__device__ float g_M3[(size_t)NV*CV];   // S1 @ x0
__device__ float g_M4[(size_t)NV*CV];   // 2*S1@(S1@x0) - x0
__device__ float g_U [(size_t)BV*NV*UV]; // u gate
__device__ int   g_cnt[2][NV];
__device__ int   g_rowptr[2][NV+1];
__device__ ull   g_ent[2][NNZ_CAP];      // packed {val:hi32, col:lo32}

// ---------------- CSR build ----------------
__global__ void k_count(const float* __restrict__ S0, const float* __restrict__ S1) {
    int row = blockIdx.x, s = blockIdx.y, t = threadIdx.x;
    const float* S = (s ? S1 : S0) + (size_t)row * NV + t * 16;
    int cnt = 0;
    #pragma unroll
    for (int j = 0; j < 16; j++) cnt += (S[j] != 0.0f);
    __shared__ int sm[256];
    sm[t] = cnt; __syncthreads();
    for (int o = 128; o > 0; o >>= 1) { if (t < o) sm[t] += sm[t + o]; __syncthreads(); }
    if (t == 0) g_cnt[s][row] = sm[0];
}

__global__ void k_scan() {
    int s = blockIdx.x, t = threadIdx.x;          // 1024 threads, 4 elems each
    int base = t * 4, v[4], sum = 0;
    #pragma unroll
    for (int i = 0; i < 4; i++) { v[i] = g_cnt[s][base + i]; sum += v[i]; }
    int lane = t & 31, w = t >> 5;
    int x = sum;
    #pragma unroll
    for (int o = 1; o < 32; o <<= 1) { int y = __shfl_up_sync(~0u, x, o); if (lane >= o) x += y; }
    __shared__ int ws[32];
    if (lane == 31) ws[w] = x;
    __syncthreads();
    if (w == 0) {
        int y = ws[lane];
        #pragma unroll
        for (int o = 1; o < 32; o <<= 1) { int z = __shfl_up_sync(~0u, y, o); if (lane >= o) y += z; }
        ws[lane] = y;
    }
    __syncthreads();
    int excl = x - sum + (w ? ws[w - 1] : 0);
    int run = excl;
    #pragma unroll
    for (int i = 0; i < 4; i++) { g_rowptr[s][base + i] = run; run += v[i]; }
    if (t == 1023) g_rowptr[s][NV] = run;
}

__global__ void k_fill(const float* __restrict__ S0, const float* __restrict__ S1) {
    int row = blockIdx.x, s = blockIdx.y, t = threadIdx.x;
    const float* S = (s ? S1 : S0) + (size_t)row * NV;
    int cnt = 0;
    #pragma unroll
    for (int j = 0; j < 16; j++) cnt += (S[t * 16 + j] != 0.0f);
    // block exclusive scan (ordered by column chunk)
    int lane = t & 31, w = t >> 5;
    int x = cnt;
    #pragma unroll
    for (int o = 1; o < 32; o <<= 1) { int y = __shfl_up_sync(~0u, x, o); if (lane >= o) x += y; }
    __shared__ int ws[8];
    if (lane == 31) ws[w] = x;
    __syncthreads();
    int woff = 0;
    for (int i = 0; i < w; i++) woff += ws[i];
    int pos = g_rowptr[s][row] + woff + x - cnt;
    for (int j = 0; j < 16; j++) {
        float v = S[t * 16 + j];
        if (v != 0.0f) {
            if (pos < NNZ_CAP) {
                ull e = ((ull)(unsigned)__float_as_uint(v) << 32) | (unsigned)(t * 16 + j);
                g_ent[s][pos] = e;
            }
            pos++;
        }
    }
}

// ---------------- build x0 for gconv1 (and inputs-part for gconv2) ----------------
__global__ void k_fillX(const float* __restrict__ inp, const float* __restrict__ hx) {
    int idx = blockIdx.x * 256 + threadIdx.x;          // over NV*CV exactly
    int n = idx / CV, col = idx - n * CV;
    int f = col >> 5, b = col & 31;
    float val;
    if (f < 2) { val = inp[(size_t)b * (NV * 2) + n * 2 + f]; g_X2[idx] = val; }
    else         val = hx[(size_t)b * (NV * UV) + n * UV + (f - 2)];
    g_X1[idx] = val;
}

// ---------------- SpMM: full-height 4096x8 column tile in smem ----------------
// pass1: M1 = S0 @ X, M3 = S1 @ X  (one tile load serves both supports)
__global__ void __launch_bounds__(512) k_spmm1(int which) {
    extern __shared__ float tile[];                    // [4096][8]
    const float* __restrict__ X = which ? g_X2 : g_X1;
    const int c0 = blockIdx.x * TW;
    const int t = threadIdx.x;
    for (int i = t; i < NV * 2; i += 512) {
        int n = i >> 1, h = i & 1;
        ((float4*)tile)[i] = *(const float4*)(X + (size_t)n * CV + c0 + h * 4);
    }
    __syncthreads();
    #pragma unroll 1
    for (int s = 0; s < 2; s++) {
        float* __restrict__ Y = s ? g_M3 : g_M1;
        const ull* __restrict__ ent = g_ent[s];
        const int* __restrict__ rp = g_rowptr[s];
        for (int r = t; r < NV; r += 512) {
            int p = rp[r], p1 = rp[r + 1];
            float4 a0 = make_float4(0,0,0,0), a1 = make_float4(0,0,0,0);
            for (; p < p1; p++) {
                ull e = ent[p];
                int c = (int)(unsigned)e;
                float v = __uint_as_float((unsigned)(e >> 32));
                float4 x0 = *(const float4*)(tile + c * TW);
                float4 x1 = *(const float4*)(tile + c * TW + 4);
                a0.x += v * x0.x; a0.y += v * x0.y; a0.z += v * x0.z; a0.w += v * x0.w;
                a1.x += v * x1.x; a1.y += v * x1.y; a1.z += v * x1.z; a1.w += v * x1.w;
            }
            float4* out = (float4*)(Y + (size_t)r * CV + c0);
            out[0] = a0; out[1] = a1;
        }
    }
}

// pass2: Y = 2 * (S_s @ Xsrc) - Xsub   (Chebyshev), Xsrc = M1/M3, Y = M2/M4
__global__ void __launch_bounds__(512) k_spmm2(int which, int s) {
    extern __shared__ float tile[];
    const float* __restrict__ X = s ? g_M3 : g_M1;
    const float* __restrict__ Xsub = which ? g_X2 : g_X1;
    float* __restrict__ Y = s ? g_M4 : g_M2;
    const int c0 = blockIdx.x * TW;
    const int t = threadIdx.x;
    for (int i = t; i < NV * 2; i += 512) {
        int n = i >> 1, h = i & 1;
        ((float4*)tile)[i] = *(const float4*)(X + (size_t)n * CV + c0 + h * 4);
    }
    __syncthreads();
    const ull* __restrict__ ent = g_ent[s];
    const int* __restrict__ rp = g_rowptr[s];
    for (int r = t; r < NV; r += 512) {
        int p = rp[r], p1 = rp[r + 1];
        float4 a0 = make_float4(0,0,0,0), a1 = make_float4(0,0,0,0);
        for (; p < p1; p++) {
            ull e = ent[p];
            int c = (int)(unsigned)e;
            float v = __uint_as_float((unsigned)(e >> 32));
            float4 x0 = *(const float4*)(tile + c * TW);
            float4 x1 = *(const float4*)(tile + c * TW + 4);
            a0.x += v * x0.x; a0.y += v * x0.y; a0.z += v * x0.z; a0.w += v * x0.w;
            a1.x += v * x1.x; a1.y += v * x1.y; a1.z += v * x1.z; a1.w += v * x1.w;
        }
        float4 s0 = *(const float4*)(Xsub + (size_t)r * CV + c0);
        float4 s1 = *(const float4*)(Xsub + (size_t)r * CV + c0 + 4);
        a0.x = 2.f*a0.x - s0.x; a0.y = 2.f*a0.y - s0.y; a0.z = 2.f*a0.z - s0.z; a0.w = 2.f*a0.w - s0.w;
        a1.x = 2.f*a1.x - s1.x; a1.y = 2.f*a1.y - s1.y; a1.z = 2.f*a1.z - s1.z; a1.w = 2.f*a1.w - s1.w;
        float4* out = (float4*)(Y + (size_t)r * CV + c0);
        out[0] = a0; out[1] = a1;
    }
}

// ---------------- dense GEMM: (B*N, 330) @ (330, OUT), fused epilogues ----------------
// Block: 4 n's x 32 b's = 128 rows, OUT cols. K = (f,m) with k = f*5+m.
// A[(b,n),(f,m)] = mat_m[n*CV + f*32 + b]  (b-contiguous loads).
// MODE 1: sigmoid; cols<64 -> r*hx written into g_X2 state slot; cols>=64 -> g_U.
// MODE 2: tanh; out = u*hx + (1-u)*c.
template<int OUT, int MODE>
__global__ void __launch_bounds__(256, 2) k_gemm(const float* __restrict__ W,
                                                 const float* __restrict__ bias,
                                                 const float* __restrict__ hx,
                                                 float* __restrict__ dout) {
    extern __shared__ float smem[];
    float* As = smem;                 // [66][128]
    float* Ws = smem + 66 * 128;      // [66][OUT]
    const int t = threadIdx.x;
    const int n0 = blockIdx.x * 4;
    constexpr int CT = OUT / 8;       // col tiles of 8
    constexpr int MR = OUT / 16;      // rows per thread (8 or 4)
    const int tr = t / CT, tc = t % CT;
    const int r0 = tr * MR, c0 = tc * 8;

    ull acc2[MR][4];
    #pragma unroll
    for (int r = 0; r < MR; r++)
        #pragma unroll
        for (int j = 0; j < 4; j++) acc2[r][j] = 0ull;

    #pragma unroll 1
    for (int m = 0; m < 5; m++) {
        const float* Mm = (m == 0) ? (MODE == 1 ? g_X1 : g_X2)
                        : (m == 1) ? g_M1 : (m == 2) ? g_M2
                        : (m == 3) ? g_M3 : g_M4;
        for (int i = t; i < 66 * 128; i += 256) {
            int b = i & 31, r2 = i >> 5;
            int f = r2 % 66, nl = r2 / 66;
            As[f * 128 + nl * 32 + b] = Mm[(size_t)(n0 + nl) * CV + f * 32 + b];
        }
        for (int i = t; i < 66 * OUT; i += 256) {
            int o = i % OUT, f = i / OUT;
            Ws[f * OUT + o] = W[(f * 5 + m) * OUT + o];
        }
        __syncthreads();
        #pragma unroll 2
        for (int f = 0; f < 66; f++) {
            ull w2[4];
            const ull* wp = (const ull*)(Ws + f * OUT + c0);
            #pragma unroll
            for (int j = 0; j < 4; j++) w2[j] = wp[j];
            const float* ap = As + f * 128 + r0;
            #pragma unroll
            for (int r = 0; r < MR; r++) {
                float a = ap[r];
                ull a2;
                asm("mov.b64 %0, {%1, %1};" : "=l"(a2) : "r"(__float_as_uint(a)));
                #pragma unroll
                for (int j = 0; j < 4; j++)
                    asm("fma.rn.f32x2 %0, %1, %2, %0;" : "+l"(acc2[r][j]) : "l"(a2), "l"(w2[j]));
            }
        }
        __syncthreads();
    }

    // epilogue
    #pragma unroll
    for (int r = 0; r < MR; r++) {
        int row = r0 + r, nl = row >> 5, b = row & 31, n = n0 + nl;
        #pragma unroll
        for (int j = 0; j < 4; j++) {
            unsigned lo, hi;
            asm("mov.b64 {%0, %1}, %2;" : "=r"(lo), "=r"(hi) : "l"(acc2[r][j]));
            float v[2] = { __uint_as_float(lo), __uint_as_float(hi) };
            #pragma unroll
            for (int q = 0; q < 2; q++) {
                int o = c0 + j * 2 + q;
                float x = v[q] + bias[o];
                if (MODE == 1) {
                    float sg = 1.0f / (1.0f + expf(-x));
                    if (o < UV) {
                        float rh = sg * hx[(size_t)b * (NV * UV) + n * UV + o];
                        g_X2[(size_t)n * CV + (2 + o) * 32 + b] = rh;
                    } else {
                        g_U[((size_t)b * NV + n) * UV + (o - UV)] = sg;
                    }
                } else {
                    float cv = tanhf(x);
                    float h = hx[(size_t)b * (NV * UV) + n * UV + o];
                    float u = g_U[((size_t)b * NV + n) * UV + o];
                    dout[(size_t)b * (NV * UV) + n * UV + o] = u * h + (1.0f - u) * cv;
                }
            }
        }
    }
}

// ---------------- launch ----------------
extern "C" void kernel_launch(void* const* d_in, const int* in_sizes, int n_in,
                              void* d_out, int out_size) {
    const float* inp = (const float*)d_in[0];
    const float* hx  = (const float*)d_in[1];
    const float* S0  = (const float*)d_in[2];
    const float* S1  = (const float*)d_in[3];
    const float* W1  = (const float*)d_in[4];
    const float* B1  = (const float*)d_in[5];
    const float* W2  = (const float*)d_in[6];
    const float* B2  = (const float*)d_in[7];
    float* out = (float*)d_out;

    const size_t tile_smem  = (size_t)NV * TW * sizeof(float);      // 131072
    const size_t gemm1_smem = (66 * 128 + 66 * 128) * sizeof(float); // 67584
    const size_t gemm2_smem = (66 * 128 + 66 * 64) * sizeof(float);  // 50688
    cudaFuncSetAttribute((const void*)k_spmm1, cudaFuncAttributeMaxDynamicSharedMemorySize, (int)tile_smem);
    cudaFuncSetAttribute((const void*)k_spmm2, cudaFuncAttributeMaxDynamicSharedMemorySize, (int)tile_smem);
    cudaFuncSetAttribute((const void*)k_gemm<128,1>, cudaFuncAttributeMaxDynamicSharedMemorySize, (int)gemm1_smem);
    cudaFuncSetAttribute((const void*)k_gemm<64,2>,  cudaFuncAttributeMaxDynamicSharedMemorySize, (int)gemm2_smem);

    dim3 gNS(NV, 2);
    k_count<<<gNS, 256>>>(S0, S1);
    k_scan<<<2, 1024>>>();
    k_fill<<<gNS, 256>>>(S0, S1);
    k_fillX<<<(NV * CV) / 256, 256>>>(inp, hx);

    // gconv 1 (state = hx)
    k_spmm1<<<NT, 512, tile_smem>>>(0);
    k_spmm2<<<NT, 512, tile_smem>>>(0, 0);
    k_spmm2<<<NT, 512, tile_smem>>>(0, 1);
    k_gemm<128,1><<<NV / 4, 256, gemm1_smem>>>(W1, B1, hx, out);

    // gconv 2 (state = r*hx, built by GEMM1 epilogue into g_X2)
    k_spmm1<<<NT, 512, tile_smem>>>(1);
    k_spmm2<<<NT, 512, tile_smem>>>(1, 0);
    k_spmm2<<<NT, 512, tile_smem>>>(1, 1);
    k_gemm<64,2><<<NV / 4, 256, gemm2_smem>>>(W2, B2, hx, out);
}

// round 5
// speedup vs baseline: 2.0755x; 2.0755x over previous
#include <cuda_runtime.h>
#include <stdint.h>
#include <math.h>

// DCGRU cell. N=4096, B=32, IN_DIM=2, U=64, K=2, 2 supports -> M=5, F=66, C=F*B=2112.
// Supports are ~1% sparse -> on-device CSR + smem-tiled SpMM (fp32, swizzled, f32x2),
// Chebyshev 2*(S@x1)-x0 folded into preprocessed weights, dense GEMMs with f32x2 FMA
// and fused sigmoid/tanh/GRU epilogues.

#define NV 4096
#define BV 32
#define FV 66
#define CV (FV*BV)        // 2112
#define UV 64
#define NNZ_CAP 300000
#define TW 8              // SpMM column-tile width
#define NT (CV/TW)        // 264 tiles

typedef unsigned long long ull;

// ---------------- device scratch ----------------
__device__ float g_X1[(size_t)NV*CV];    // x0 for gconv1
__device__ float g_X2[(size_t)NV*CV];    // x0 for gconv2 (inputs + r*hx)
__device__ float g_M1[(size_t)NV*CV];    // S0 @ x0
__device__ float g_M2[(size_t)NV*CV];    // S0 @ M1   (Chebyshev folded into weights)
__device__ float g_M3[(size_t)NV*CV];    // S1 @ x0
__device__ float g_M4[(size_t)NV*CV];    // S1 @ M3
__device__ float g_U [(size_t)BV*NV*UV]; // u gate
__device__ float g_W1p[330*128];
__device__ float g_W2p[330*64];
__device__ int   g_cnt[2][NV];
__device__ int   g_rowptr[2][NV+1];
__device__ ull   g_ent[2][NNZ_CAP];      // packed {val:hi32, col:lo32}

// ---------------- CSR build ----------------
__global__ void k_count(const float* __restrict__ S0, const float* __restrict__ S1) {
    int row = blockIdx.x, s = blockIdx.y, t = threadIdx.x;
    const float4* S = (const float4*)((s ? S1 : S0) + (size_t)row * NV) + t * 4;
    int cnt = 0;
    #pragma unroll
    for (int j = 0; j < 4; j++) {
        float4 v = S[j];
        cnt += (v.x != 0.0f) + (v.y != 0.0f) + (v.z != 0.0f) + (v.w != 0.0f);
    }
    __shared__ int sm[256];
    sm[t] = cnt; __syncthreads();
    for (int o = 128; o > 0; o >>= 1) { if (t < o) sm[t] += sm[t + o]; __syncthreads(); }
    if (t == 0) g_cnt[s][row] = sm[0];
}

__global__ void k_scan() {
    int s = blockIdx.x, t = threadIdx.x;          // 1024 threads, 4 rows each
    int base = t * 4, v[4], sum = 0;
    #pragma unroll
    for (int i = 0; i < 4; i++) { v[i] = g_cnt[s][base + i]; sum += v[i]; }
    int lane = t & 31, w = t >> 5;
    int x = sum;
    #pragma unroll
    for (int o = 1; o < 32; o <<= 1) { int y = __shfl_up_sync(~0u, x, o); if (lane >= o) x += y; }
    __shared__ int ws[32];
    if (lane == 31) ws[w] = x;
    __syncthreads();
    if (w == 0) {
        int y = ws[lane];
        #pragma unroll
        for (int o = 1; o < 32; o <<= 1) { int z = __shfl_up_sync(~0u, y, o); if (lane >= o) y += z; }
        ws[lane] = y;
    }
    __syncthreads();
    int excl = x - sum + (w ? ws[w - 1] : 0);
    int run = excl;
    #pragma unroll
    for (int i = 0; i < 4; i++) { g_rowptr[s][base + i] = run; run += v[i]; }
    if (t == 1023) g_rowptr[s][NV] = run;
}

__global__ void k_fill(const float* __restrict__ S0, const float* __restrict__ S1) {
    int row = blockIdx.x, s = blockIdx.y, t = threadIdx.x;
    const float* S = (s ? S1 : S0) + (size_t)row * NV;
    float4 va[4];
    #pragma unroll
    for (int j = 0; j < 4; j++) va[j] = ((const float4*)S)[t * 4 + j];
    const float* vf = (const float*)va;
    int cnt = 0;
    #pragma unroll
    for (int j = 0; j < 16; j++) cnt += (vf[j] != 0.0f);
    int lane = t & 31, w = t >> 5;
    int x = cnt;
    #pragma unroll
    for (int o = 1; o < 32; o <<= 1) { int y = __shfl_up_sync(~0u, x, o); if (lane >= o) x += y; }
    __shared__ int ws[8];
    if (lane == 31) ws[w] = x;
    __syncthreads();
    int woff = 0;
    for (int i = 0; i < w; i++) woff += ws[i];
    int pos = g_rowptr[s][row] + woff + x - cnt;
    #pragma unroll
    for (int j = 0; j < 16; j++) {
        float v = vf[j];
        if (v != 0.0f) {
            if (pos < NNZ_CAP) {
                ull e = ((ull)(unsigned)__float_as_uint(v) << 32) | (unsigned)(t * 16 + j);
                g_ent[s][pos] = e;
            }
            pos++;
        }
    }
}

// ---------------- weight preprocessing (fold Chebyshev 2x-x0 into W) ----------------
// y = W0 x0 + W1 M1 + W2 (2 M2' - x0) + W3 M3 + W4 (2 M4' - x0)
//   = (W0-W2-W4) x0 + W1 M1 + 2W2 M2' + W3 M3 + 2W4 M4'
__global__ void k_wprep(const float* __restrict__ W1, const float* __restrict__ W2) {
    int idx = blockIdx.x * 256 + threadIdx.x;
    if (idx < 330 * 128) {
        int k = idx >> 7, m = k % 5;
        float v;
        if (m == 0)      v = W1[idx] - W1[idx + 2*128] - W1[idx + 4*128];
        else if (m == 2 || m == 4) v = 2.0f * W1[idx];
        else             v = W1[idx];
        g_W1p[idx] = v;
    } else {
        int j = idx - 330 * 128;
        if (j < 330 * 64) {
            int k = j >> 6, m = k % 5;
            float v;
            if (m == 0)      v = W2[j] - W2[j + 2*64] - W2[j + 4*64];
            else if (m == 2 || m == 4) v = 2.0f * W2[j];
            else             v = W2[j];
            g_W2p[j] = v;
        }
    }
}

// ---------------- build x0 for gconv1 (and inputs-part for gconv2) ----------------
__global__ void k_fillX(const float* __restrict__ inp, const float* __restrict__ hx) {
    int idx = blockIdx.x * 256 + threadIdx.x;          // over NV*CV
    int n = idx / CV, col = idx - n * CV;
    int f = col >> 5, b = col & 31;
    float val;
    if (f < 2) { val = inp[(size_t)b * (NV * 2) + n * 2 + f]; g_X2[idx] = val; }
    else         val = hx[(size_t)b * (NV * UV) + n * UV + (f - 2)];
    g_X1[idx] = val;
}

// ---------------- SpMM core ----------------
// Tile: full-height 4096 x 8 fp32 column stripe in smem, stored as 16B units with
// XOR swizzle i' = i ^ ((i>>3)&7) so random-row gathers spread over all 8 bank-quads.
__device__ __forceinline__ void load_tile(ulonglong2* tq, const float* __restrict__ X,
                                          int c0, int t) {
    #pragma unroll
    for (int k = 0; k < 8; k++) {
        int j = t + (k << 10);                       // 16B-unit index, 0..8191
        int n = j >> 1, h = j & 1;
        ulonglong2 d = *(const ulonglong2*)(X + (size_t)n * CV + c0 + (h << 2));
        tq[j ^ ((j >> 3) & 7)] = d;
    }
}

__device__ __forceinline__ void accum(ull e, const ulonglong2* tq,
                                      ull& a0, ull& a1, ull& a2, ull& a3) {
    unsigned c = (unsigned)e;
    unsigned vb = (unsigned)(e >> 32);
    ull v2; asm("mov.b64 %0, {%1, %1};" : "=l"(v2) : "r"(vb));
    int u = (int)(c << 1);
    int i0 = u ^ ((u >> 3) & 7);                     // swizzled unit for cols 0-3
    ulonglong2 q0 = tq[i0];
    ulonglong2 q1 = tq[i0 ^ 1];                      // cols 4-7 (u even => swz(u+1)=swz(u)^1)
    asm("fma.rn.f32x2 %0, %1, %2, %0;" : "+l"(a0) : "l"(v2), "l"(q0.x));
    asm("fma.rn.f32x2 %0, %1, %2, %0;" : "+l"(a1) : "l"(v2), "l"(q0.y));
    asm("fma.rn.f32x2 %0, %1, %2, %0;" : "+l"(a2) : "l"(v2), "l"(q1.x));
    asm("fma.rn.f32x2 %0, %1, %2, %0;" : "+l"(a3) : "l"(v2), "l"(q1.y));
}

__device__ __forceinline__ void sweep(const ulonglong2* tq, const ull* __restrict__ ent,
                                      const int* __restrict__ rp, float* __restrict__ Y,
                                      int c0, int t) {
    for (int r = t; r < NV; r += 1024) {
        int p = rp[r], p1 = rp[r + 1];
        ull a0 = 0, a1 = 0, a2 = 0, a3 = 0;
        for (; p + 4 <= p1; p += 4) {                // batched entry loads -> MLP>=4
            ull e0 = __ldg(ent + p),     e1 = __ldg(ent + p + 1);
            ull e2 = __ldg(ent + p + 2), e3 = __ldg(ent + p + 3);
            accum(e0, tq, a0, a1, a2, a3);
            accum(e1, tq, a0, a1, a2, a3);
            accum(e2, tq, a0, a1, a2, a3);
            accum(e3, tq, a0, a1, a2, a3);
        }
        for (; p < p1; p++) accum(__ldg(ent + p), tq, a0, a1, a2, a3);
        ulonglong2 o0, o1; o0.x = a0; o0.y = a1; o1.x = a2; o1.y = a3;
        *(ulonglong2*)(Y + (size_t)r * CV + c0)     = o0;
        *(ulonglong2*)(Y + (size_t)r * CV + c0 + 4) = o1;
    }
}

// first hop: M1 = S0 @ X, M3 = S1 @ X (one tile load serves both supports)
__global__ void __launch_bounds__(1024) k_spmmA(int which) {
    extern __shared__ ulonglong2 tq[];
    int t = threadIdx.x, c0 = blockIdx.x * TW;
    load_tile(tq, which ? g_X2 : g_X1, c0, t);
    __syncthreads();
    sweep(tq, g_ent[0], g_rowptr[0], g_M1, c0, t);
    sweep(tq, g_ent[1], g_rowptr[1], g_M3, c0, t);
}

// second hop: M2 = S0 @ M1, M4 = S1 @ M3 (grid.y = support)
__global__ void __launch_bounds__(1024) k_spmmB() {
    extern __shared__ ulonglong2 tq[];
    int t = threadIdx.x, c0 = blockIdx.x * TW, s = blockIdx.y;
    load_tile(tq, s ? g_M3 : g_M1, c0, t);
    __syncthreads();
    sweep(tq, g_ent[s], g_rowptr[s], s ? g_M4 : g_M2, c0, t);
}

// ---------------- dense GEMM: (B*N, 330) @ (330, OUT), fused epilogues ----------------
// Weights are read from the device-global preprocessed arrays g_W1p/g_W2p directly
// (passing a __device__ symbol as a host-side kernel arg gives the host shadow
// address -> garbage; that was the R2 bug).
// Block: 4 n's x 32 b's = 128 rows, OUT cols. k = f*5+m.
// MODE 1: sigmoid; cols<64 -> r*hx into g_X2 state slot; cols>=64 -> g_U.
// MODE 2: tanh; out = u*hx + (1-u)*c.
template<int OUT, int MODE>
__global__ void __launch_bounds__(256, 2) k_gemm(const float* __restrict__ bias,
                                                 const float* __restrict__ hx,
                                                 float* __restrict__ dout) {
    extern __shared__ float smem[];
    float* As = smem;                 // [66][128]
    float* Ws = smem + 66 * 128;      // [66][OUT]
    const float* __restrict__ W = (MODE == 1) ? g_W1p : g_W2p;
    const int t = threadIdx.x;
    const int n0 = blockIdx.x * 4;
    constexpr int CT = OUT / 8;
    constexpr int MR = OUT / 16;
    const int tr = t / CT, tc = t % CT;
    const int r0 = tr * MR, c0 = tc * 8;

    ull acc2[MR][4];
    #pragma unroll
    for (int r = 0; r < MR; r++)
        #pragma unroll
        for (int j = 0; j < 4; j++) acc2[r][j] = 0ull;

    #pragma unroll 1
    for (int m = 0; m < 5; m++) {
        const float* Mm = (m == 0) ? (MODE == 1 ? g_X1 : g_X2)
                        : (m == 1) ? g_M1 : (m == 2) ? g_M2
                        : (m == 3) ? g_M3 : g_M4;
        for (int i = t; i < 66 * 128; i += 256) {
            int b = i & 31, r2 = i >> 5;
            int f = r2 % 66, nl = r2 / 66;
            As[f * 128 + nl * 32 + b] = Mm[(size_t)(n0 + nl) * CV + f * 32 + b];
        }
        for (int i = t; i < 66 * OUT; i += 256) {
            int o = i % OUT, f = i / OUT;
            Ws[f * OUT + o] = W[(f * 5 + m) * OUT + o];
        }
        __syncthreads();
        #pragma unroll 2
        for (int f = 0; f < 66; f++) {
            ull w2[4];
            const ull* wp = (const ull*)(Ws + f * OUT + c0);
            #pragma unroll
            for (int j = 0; j < 4; j++) w2[j] = wp[j];
            const float* ap = As + f * 128 + r0;
            #pragma unroll
            for (int r = 0; r < MR; r++) {
                float a = ap[r];
                ull a2;
                asm("mov.b64 %0, {%1, %1};" : "=l"(a2) : "r"(__float_as_uint(a)));
                #pragma unroll
                for (int j = 0; j < 4; j++)
                    asm("fma.rn.f32x2 %0, %1, %2, %0;" : "+l"(acc2[r][j]) : "l"(a2), "l"(w2[j]));
            }
        }
        __syncthreads();
    }

    #pragma unroll
    for (int r = 0; r < MR; r++) {
        int row = r0 + r, nl = row >> 5, b = row & 31, n = n0 + nl;
        #pragma unroll
        for (int j = 0; j < 4; j++) {
            unsigned lo, hi;
            asm("mov.b64 {%0, %1}, %2;" : "=r"(lo), "=r"(hi) : "l"(acc2[r][j]));
            float v[2] = { __uint_as_float(lo), __uint_as_float(hi) };
            #pragma unroll
            for (int q = 0; q < 2; q++) {
                int o = c0 + j * 2 + q;
                float x = v[q] + bias[o];
                if (MODE == 1) {
                    float sg = 1.0f / (1.0f + expf(-x));
                    if (o < UV) {
                        float rh = sg * hx[(size_t)b * (NV * UV) + n * UV + o];
                        g_X2[(size_t)n * CV + (2 + o) * 32 + b] = rh;
                    } else {
                        g_U[((size_t)b * NV + n) * UV + (o - UV)] = sg;
                    }
                } else {
                    float cv = tanhf(x);
                    float h = hx[(size_t)b * (NV * UV) + n * UV + o];
                    float u = g_U[((size_t)b * NV + n) * UV + o];
                    dout[(size_t)b * (NV * UV) + n * UV + o] = u * h + (1.0f - u) * cv;
                }
            }
        }
    }
}

// ---------------- launch ----------------
extern "C" void kernel_launch(void* const* d_in, const int* in_sizes, int n_in,
                              void* d_out, int out_size) {
    const float* inp = (const float*)d_in[0];
    const float* hx  = (const float*)d_in[1];
    const float* S0  = (const float*)d_in[2];
    const float* S1  = (const float*)d_in[3];
    const float* W1  = (const float*)d_in[4];
    const float* B1  = (const float*)d_in[5];
    const float* W2  = (const float*)d_in[6];
    const float* B2  = (const float*)d_in[7];
    float* out = (float*)d_out;

    const size_t tile_smem  = (size_t)NV * TW * sizeof(float);       // 131072
    const size_t gemm1_smem = (66 * 128 + 66 * 128) * sizeof(float); // 67584
    const size_t gemm2_smem = (66 * 128 + 66 * 64) * sizeof(float);  // 50688
    cudaFuncSetAttribute(k_spmmA, cudaFuncAttributeMaxDynamicSharedMemorySize, (int)tile_smem);
    cudaFuncSetAttribute(k_spmmB, cudaFuncAttributeMaxDynamicSharedMemorySize, (int)tile_smem);
    cudaFuncSetAttribute(k_gemm<128,1>, cudaFuncAttributeMaxDynamicSharedMemorySize, (int)gemm1_smem);
    cudaFuncSetAttribute(k_gemm<64,2>,  cudaFuncAttributeMaxDynamicSharedMemorySize, (int)gemm2_smem);

    dim3 gNS(NV, 2);
    k_count<<<gNS, 256>>>(S0, S1);
    k_scan<<<2, 1024>>>();
    k_fill<<<gNS, 256>>>(S0, S1);
    k_fillX<<<(NV * CV) / 256, 256>>>(inp, hx);
    k_wprep<<<(330 * 128 + 330 * 64 + 255) / 256, 256>>>(W1, W2);

    // gconv 1 (state = hx)
    k_spmmA<<<NT, 1024, tile_smem>>>(0);
    k_spmmB<<<dim3(NT, 2), 1024, tile_smem>>>();
    k_gemm<128,1><<<NV / 4, 256, gemm1_smem>>>(B1, hx, out);

    // gconv 2 (state = r*hx, built by GEMM1 epilogue into g_X2)
    k_spmmA<<<NT, 1024, tile_smem>>>(1);
    k_spmmB<<<dim3(NT, 2), 1024, tile_smem>>>();
    k_gemm<64,2><<<NV / 4, 256, gemm2_smem>>>(B2, hx, out);
}

// round 6
// speedup vs baseline: 2.6693x; 1.2861x over previous
#include <cuda_runtime.h>
#include <stdint.h>
#include <math.h>

// DCGRU cell. N=4096, B=32, IN_DIM=2, U=64, K=2, 2 supports -> M=5, F=66, C=F*B=2112.
// Supports ~1% sparse -> on-device SELL-32 (warp-contiguous padded entries) + smem-tiled
// SpMM (fp32, XOR-swizzled 16B units, f32x2 FMA). Chebyshev 2*(S@x1)-x0 folded into
// preprocessed weights. Dense GEMMs with f32x2 FMA and fused sigmoid/tanh/GRU epilogues.

#define NV 4096
#define BV 32
#define FV 66
#define CV (FV*BV)        // 2112
#define UV 64
#define NG 128            // row groups of 32
#define SELL_CAP 420000
#define TW 8              // SpMM column-tile width
#define NT (CV/TW)        // 264 tiles

typedef unsigned long long ull;

// ---------------- device scratch ----------------
__device__ float g_X1[(size_t)NV*CV];    // x0 for gconv1
__device__ float g_X2[(size_t)NV*CV];    // x0 for gconv2 (inputs + r*hx)
__device__ float g_M1[(size_t)NV*CV];    // S0 @ x0
__device__ float g_M2[(size_t)NV*CV];    // S0 @ M1   (Chebyshev folded into weights)
__device__ float g_M3[(size_t)NV*CV];    // S1 @ x0
__device__ float g_M4[(size_t)NV*CV];    // S1 @ M3
__device__ float g_U [(size_t)BV*NV*UV]; // u gate
__device__ float g_W1p[330*128];
__device__ float g_W2p[330*64];
__device__ int   g_cnt[2][NV];           // per-row nnz
__device__ int   g_gw [2][NG];           // per-group (32 rows) padded width
__device__ int   g_goff[2][NG+1];        // group entry offsets
__device__ ull   g_ent[2][SELL_CAP];     // SELL: {val:hi32, col:lo32} at goff + j*32 + lane

// ---------------- fused prep: fillX + per-row count + weight fold ----------------
// y = W0 x0 + W1 M1 + W2 (2 M2' - x0) + W3 M3 + W4 (2 M4' - x0)
//   = (W0-W2-W4) x0 + W1 M1 + 2W2 M2' + W3 M3 + 2W4 M4'
#define NB_FILLX ((NV*CV)/256)           // 33792
#define NB_COUNT (2*NV)                  // 8192
#define NB_WPREP (((330*128+330*64)+255)/256) // 248
__global__ void k_prep(const float* __restrict__ inp, const float* __restrict__ hx,
                       const float* __restrict__ S0, const float* __restrict__ S1,
                       const float* __restrict__ W1, const float* __restrict__ W2) {
    int blk = blockIdx.x, t = threadIdx.x;
    if (blk < NB_FILLX) {
        int idx = blk * 256 + t;
        int n = idx / CV, col = idx - n * CV;
        int f = col >> 5, b = col & 31;
        float val;
        if (f < 2) { val = inp[(size_t)b * (NV * 2) + n * 2 + f]; g_X2[idx] = val; }
        else         val = hx[(size_t)b * (NV * UV) + n * UV + (f - 2)];
        g_X1[idx] = val;
    } else if (blk < NB_FILLX + NB_COUNT) {
        int b2 = blk - NB_FILLX;
        int s = b2 >> 12, row = b2 & (NV - 1);
        const float4* S = (const float4*)((s ? S1 : S0) + (size_t)row * NV) + t * 4;
        int cnt = 0;
        #pragma unroll
        for (int j = 0; j < 4; j++) {
            float4 v = S[j];
            cnt += (v.x != 0.0f) + (v.y != 0.0f) + (v.z != 0.0f) + (v.w != 0.0f);
        }
        __shared__ int sm[256];
        sm[t] = cnt; __syncthreads();
        for (int o = 128; o > 0; o >>= 1) { if (t < o) sm[t] += sm[t + o]; __syncthreads(); }
        if (t == 0) g_cnt[s][row] = sm[0];
    } else {
        int idx = (blk - NB_FILLX - NB_COUNT) * 256 + t;
        if (idx < 330 * 128) {
            int k = idx >> 7, m = k % 5;
            float v;
            if (m == 0)      v = W1[idx] - W1[idx + 2*128] - W1[idx + 4*128];
            else if (m == 2 || m == 4) v = 2.0f * W1[idx];
            else             v = W1[idx];
            g_W1p[idx] = v;
        } else if (idx < 330 * 128 + 330 * 64) {
            int j = idx - 330 * 128;
            int k = j >> 6, m = k % 5;
            float v;
            if (m == 0)      v = W2[j] - W2[j + 2*64] - W2[j + 4*64];
            else if (m == 2 || m == 4) v = 2.0f * W2[j];
            else             v = W2[j];
            g_W2p[j] = v;
        }
    }
}

// ---------------- group widths + offsets (grid 2, block 128) ----------------
__global__ void k_groups() {
    int s = blockIdx.x, g = threadIdx.x;
    int mx = 0;
    #pragma unroll 8
    for (int i = 0; i < 32; i++) mx = max(mx, g_cnt[s][g * 32 + i]);
    g_gw[s][g] = mx;
    __shared__ int sw[NG];
    int v = mx * 32;
    sw[g] = v; __syncthreads();
    for (int o = 1; o < NG; o <<= 1) {
        int y = (g >= o) ? sw[g - o] : 0;
        __syncthreads();
        sw[g] += y;
        __syncthreads();
    }
    g_goff[s][g] = sw[g] - v;
    if (g == NG - 1) g_goff[s][NG] = sw[g];
}

// ---------------- SELL fill (grid (4096,2), block 256) ----------------
__global__ void k_fill(const float* __restrict__ S0, const float* __restrict__ S1) {
    int row = blockIdx.x, s = blockIdx.y, t = threadIdx.x;
    const float* S = (s ? S1 : S0) + (size_t)row * NV;
    float4 va[4];
    #pragma unroll
    for (int j = 0; j < 4; j++) va[j] = ((const float4*)S)[t * 4 + j];
    const float* vf = (const float*)va;
    int cnt = 0;
    #pragma unroll
    for (int j = 0; j < 16; j++) cnt += (vf[j] != 0.0f);
    int lane = t & 31, w = t >> 5;
    int x = cnt;
    #pragma unroll
    for (int o = 1; o < 32; o <<= 1) { int y = __shfl_up_sync(~0u, x, o); if (lane >= o) x += y; }
    __shared__ int ws[8];
    if (lane == 31) ws[w] = x;
    __syncthreads();
    int woff = 0;
    for (int i = 0; i < w; i++) woff += ws[i];
    int g = row >> 5, rl = row & 31;
    int base = g_goff[s][g] + rl;
    int width = g_gw[s][g];
    int rank = woff + x - cnt;                    // exclusive rank within row
    #pragma unroll
    for (int j = 0; j < 16; j++) {
        float v = vf[j];
        if (v != 0.0f) {
            int dst = base + rank * 32;
            if (dst < SELL_CAP)
                g_ent[s][dst] = ((ull)(unsigned)__float_as_uint(v) << 32) | (unsigned)(t * 16 + j);
            rank++;
        }
    }
    // pad [cnt_row, width) with {0,0}
    int cr = g_cnt[s][row];
    for (int j = cr + t; j < width; j += 256) {
        int dst = base + j * 32;
        if (dst < SELL_CAP) g_ent[s][dst] = 0ull;
    }
}

// ---------------- SpMM core ----------------
// Tile: full-height 4096 x 8 fp32 stripe in smem as 16B units, XOR swizzle
// i' = i ^ ((i>>3)&7) spreads random-row gathers over all 8 bank-quads.
__device__ __forceinline__ void load_tile(ulonglong2* tq, const float* __restrict__ X,
                                          int c0, int t) {
    #pragma unroll
    for (int k = 0; k < 8; k++) {
        int j = t + (k << 10);                       // unit index 0..8191
        int n = j >> 1, h = j & 1;
        ulonglong2 d = *(const ulonglong2*)(X + (size_t)n * CV + c0 + (h << 2));
        tq[j ^ ((j >> 3) & 7)] = d;
    }
}

__device__ __forceinline__ void accum(ull e, const ulonglong2* tq,
                                      ull& a0, ull& a1, ull& a2, ull& a3) {
    unsigned c = (unsigned)e;
    unsigned vb = (unsigned)(e >> 32);
    ull v2; asm("mov.b64 %0, {%1, %1};" : "=l"(v2) : "r"(vb));
    int u = (int)(c << 1);
    int i0 = u ^ ((u >> 3) & 7);                     // swizzled unit, cols 0-3
    ulonglong2 q0 = tq[i0];
    ulonglong2 q1 = tq[i0 ^ 1];                      // cols 4-7 (u even => swz(u+1)=swz(u)^1)
    asm("fma.rn.f32x2 %0, %1, %2, %0;" : "+l"(a0) : "l"(v2), "l"(q0.x));
    asm("fma.rn.f32x2 %0, %1, %2, %0;" : "+l"(a1) : "l"(v2), "l"(q0.y));
    asm("fma.rn.f32x2 %0, %1, %2, %0;" : "+l"(a2) : "l"(v2), "l"(q1.x));
    asm("fma.rn.f32x2 %0, %1, %2, %0;" : "+l"(a3) : "l"(v2), "l"(q1.y));
}

// SELL sweep: warp w handles groups w, w+32, w+64, w+96; lane = row within group.
// Entry loads are warp-contiguous 256B (nL=2 wavefronts per LDG).
__device__ __forceinline__ void sweep(const ulonglong2* tq, const ull* __restrict__ ent,
                                      const int* __restrict__ goff, const int* __restrict__ gw,
                                      float* __restrict__ Y, int c0, int t) {
    int lane = t & 31, w = t >> 5;
    #pragma unroll 1
    for (int g = w; g < NG; g += 32) {
        const ull* ep = ent + goff[g] + lane;
        int width = gw[g];
        ull a0 = 0, a1 = 0, a2 = 0, a3 = 0;
        int j = 0;
        for (; j + 4 <= width; j += 4) {
            ull e0 = __ldg(ep + (j    ) * 32);
            ull e1 = __ldg(ep + (j + 1) * 32);
            ull e2 = __ldg(ep + (j + 2) * 32);
            ull e3 = __ldg(ep + (j + 3) * 32);
            accum(e0, tq, a0, a1, a2, a3);
            accum(e1, tq, a0, a1, a2, a3);
            accum(e2, tq, a0, a1, a2, a3);
            accum(e3, tq, a0, a1, a2, a3);
        }
        for (; j < width; j++) accum(__ldg(ep + j * 32), tq, a0, a1, a2, a3);
        int r = g * 32 + lane;
        ulonglong2 o0, o1; o0.x = a0; o0.y = a1; o1.x = a2; o1.y = a3;
        *(ulonglong2*)(Y + (size_t)r * CV + c0)     = o0;
        *(ulonglong2*)(Y + (size_t)r * CV + c0 + 4) = o1;
    }
}

// first hop: M1 = S0 @ X, M3 = S1 @ X (one tile load serves both supports)
__global__ void __launch_bounds__(1024) k_spmmA(int which) {
    extern __shared__ ulonglong2 tq[];
    int t = threadIdx.x, c0 = blockIdx.x * TW;
    load_tile(tq, which ? g_X2 : g_X1, c0, t);
    __syncthreads();
    sweep(tq, g_ent[0], g_goff[0], g_gw[0], g_M1, c0, t);
    sweep(tq, g_ent[1], g_goff[1], g_gw[1], g_M3, c0, t);
}

// second hop: M2 = S0 @ M1, M4 = S1 @ M3 (grid.y = support)
__global__ void __launch_bounds__(1024) k_spmmB() {
    extern __shared__ ulonglong2 tq[];
    int t = threadIdx.x, c0 = blockIdx.x * TW, s = blockIdx.y;
    load_tile(tq, s ? g_M3 : g_M1, c0, t);
    __syncthreads();
    sweep(tq, g_ent[s], g_goff[s], g_gw[s], s ? g_M4 : g_M2, c0, t);
}

// ---------------- dense GEMM: (B*N, 330) @ (330, OUT), fused epilogues ----------------
// Weights read directly from device globals (host-side __device__ symbol args = R2 bug).
// Block: 4 n's x 32 b's = 128 rows, OUT cols. k = f*5+m.
// MODE 1: sigmoid; cols<64 -> r*hx into g_X2 state slot; cols>=64 -> g_U.
// MODE 2: tanh; out = u*hx + (1-u)*c.
template<int OUT, int MODE>
__global__ void __launch_bounds__(256, 2) k_gemm(const float* __restrict__ bias,
                                                 const float* __restrict__ hx,
                                                 float* __restrict__ dout) {
    extern __shared__ float smem[];
    float* As = smem;                 // [66][128]
    float* Ws = smem + 66 * 128;      // [66][OUT]
    const float* __restrict__ W = (MODE == 1) ? g_W1p : g_W2p;
    const int t = threadIdx.x;
    const int n0 = blockIdx.x * 4;
    constexpr int CT = OUT / 8;
    constexpr int MR = OUT / 16;
    const int tr = t / CT, tc = t % CT;
    const int r0 = tr * MR, c0 = tc * 8;

    ull acc2[MR][4];
    #pragma unroll
    for (int r = 0; r < MR; r++)
        #pragma unroll
        for (int j = 0; j < 4; j++) acc2[r][j] = 0ull;

    #pragma unroll 1
    for (int m = 0; m < 5; m++) {
        const float* Mm = (m == 0) ? (MODE == 1 ? g_X1 : g_X2)
                        : (m == 1) ? g_M1 : (m == 2) ? g_M2
                        : (m == 3) ? g_M3 : g_M4;
        for (int i = t; i < 66 * 128; i += 256) {
            int b = i & 31, r2 = i >> 5;
            int f = r2 % 66, nl = r2 / 66;
            As[f * 128 + nl * 32 + b] = Mm[(size_t)(n0 + nl) * CV + f * 32 + b];
        }
        for (int i = t; i < 66 * OUT; i += 256) {
            int o = i % OUT, f = i / OUT;
            Ws[f * OUT + o] = W[(f * 5 + m) * OUT + o];
        }
        __syncthreads();
        #pragma unroll 2
        for (int f = 0; f < 66; f++) {
            ull w2[4];
            const ull* wp = (const ull*)(Ws + f * OUT + c0);
            #pragma unroll
            for (int j = 0; j < 4; j++) w2[j] = wp[j];
            const float* ap = As + f * 128 + r0;
            #pragma unroll
            for (int r = 0; r < MR; r++) {
                float a = ap[r];
                ull a2;
                asm("mov.b64 %0, {%1, %1};" : "=l"(a2) : "r"(__float_as_uint(a)));
                #pragma unroll
                for (int j = 0; j < 4; j++)
                    asm("fma.rn.f32x2 %0, %1, %2, %0;" : "+l"(acc2[r][j]) : "l"(a2), "l"(w2[j]));
            }
        }
        __syncthreads();
    }

    #pragma unroll
    for (int r = 0; r < MR; r++) {
        int row = r0 + r, nl = row >> 5, b = row & 31, n = n0 + nl;
        #pragma unroll
        for (int j = 0; j < 4; j++) {
            unsigned lo, hi;
            asm("mov.b64 {%0, %1}, %2;" : "=r"(lo), "=r"(hi) : "l"(acc2[r][j]));
            float v[2] = { __uint_as_float(lo), __uint_as_float(hi) };
            #pragma unroll
            for (int q = 0; q < 2; q++) {
                int o = c0 + j * 2 + q;
                float x = v[q] + bias[o];
                if (MODE == 1) {
                    float sg = 1.0f / (1.0f + expf(-x));
                    if (o < UV) {
                        float rh = sg * hx[(size_t)b * (NV * UV) + n * UV + o];
                        g_X2[(size_t)n * CV + (2 + o) * 32 + b] = rh;
                    } else {
                        g_U[((size_t)b * NV + n) * UV + (o - UV)] = sg;
                    }
                } else {
                    float cv = tanhf(x);
                    float h = hx[(size_t)b * (NV * UV) + n * UV + o];
                    float u = g_U[((size_t)b * NV + n) * UV + o];
                    dout[(size_t)b * (NV * UV) + n * UV + o] = u * h + (1.0f - u) * cv;
                }
            }
        }
    }
}

// ---------------- launch ----------------
extern "C" void kernel_launch(void* const* d_in, const int* in_sizes, int n_in,
                              void* d_out, int out_size) {
    const float* inp = (const float*)d_in[0];
    const float* hx  = (const float*)d_in[1];
    const float* S0  = (const float*)d_in[2];
    const float* S1  = (const float*)d_in[3];
    const float* W1  = (const float*)d_in[4];
    const float* B1  = (const float*)d_in[5];
    const float* W2  = (const float*)d_in[6];
    const float* B2  = (const float*)d_in[7];
    float* out = (float*)d_out;

    const size_t tile_smem  = (size_t)NV * TW * sizeof(float);       // 131072
    const size_t gemm1_smem = (66 * 128 + 66 * 128) * sizeof(float); // 67584
    const size_t gemm2_smem = (66 * 128 + 66 * 64) * sizeof(float);  // 50688
    cudaFuncSetAttribute(k_spmmA, cudaFuncAttributeMaxDynamicSharedMemorySize, (int)tile_smem);
    cudaFuncSetAttribute(k_spmmB, cudaFuncAttributeMaxDynamicSharedMemorySize, (int)tile_smem);
    cudaFuncSetAttribute(k_gemm<128,1>, cudaFuncAttributeMaxDynamicSharedMemorySize, (int)gemm1_smem);
    cudaFuncSetAttribute(k_gemm<64,2>,  cudaFuncAttributeMaxDynamicSharedMemorySize, (int)gemm2_smem);

    k_prep<<<NB_FILLX + NB_COUNT + NB_WPREP, 256>>>(inp, hx, S0, S1, W1, W2);
    k_groups<<<2, NG>>>();
    k_fill<<<dim3(NV, 2), 256>>>(S0, S1);

    // gconv 1 (state = hx)
    k_spmmA<<<NT, 1024, tile_smem>>>(0);
    k_spmmB<<<dim3(NT, 2), 1024, tile_smem>>>();
    k_gemm<128,1><<<NV / 4, 256, gemm1_smem>>>(B1, hx, out);

    // gconv 2 (state = r*hx, built by GEMM1 epilogue into g_X2)
    k_spmmA<<<NT, 1024, tile_smem>>>(1);
    k_spmmB<<<dim3(NT, 2), 1024, tile_smem>>>();
    k_gemm<64,2><<<NV / 4, 256, gemm2_smem>>>(B2, hx, out);
}

// round 7
// speedup vs baseline: 3.8826x; 1.4545x over previous
#include <cuda_runtime.h>
#include <cuda_fp16.h>
#include <stdint.h>
#include <math.h>

// DCGRU cell. N=4096, B=32, IN_DIM=2, U=64, K=2, 2 supports -> M=5, F=66, C=F*B=2112.
// Supports ~1% sparse -> on-device SELL-32 + smem-tiled SpMM. Intermediate matrices
// stored fp16 (halves the smem-crossbar gather bytes, the binding resource per R6 ncu);
// all accumulation fp32. Chebyshev folded into weights. Dense GEMMs f32x2 FMA with
// fused sigmoid/tanh/GRU epilogues.

#define NV 4096
#define BV 32
#define FV 66
#define CV (FV*BV)        // 2112
#define UV 64
#define NG 128            // row groups of 32
#define SELL_CAP 420000
#define TW 8              // SpMM column-tile width
#define NT (CV/TW)        // 264 tiles

typedef unsigned long long ull;

// ---------------- device scratch ----------------
__device__ __align__(16) __half g_X1[(size_t)NV*CV];  // x0 for gconv1
__device__ __align__(16) __half g_X2[(size_t)NV*CV];  // x0 for gconv2 (inputs + r*hx)
__device__ __align__(16) __half g_M1[(size_t)NV*CV];  // S0 @ x0
__device__ __align__(16) __half g_M2[(size_t)NV*CV];  // S0 @ M1 (Chebyshev in weights)
__device__ __align__(16) __half g_M3[(size_t)NV*CV];  // S1 @ x0
__device__ __align__(16) __half g_M4[(size_t)NV*CV];  // S1 @ M3
__device__ float g_U [(size_t)BV*NV*UV];              // u gate (fp32)
__device__ float g_W1p[330*128];
__device__ float g_W2p[330*64];
__device__ int   g_cnt[2][NV];           // per-row nnz
__device__ int   g_gw [2][NG];           // per-group (32 rows) padded width
__device__ int   g_goff[2][NG+1];        // group entry offsets
__device__ ull   g_ent[2][SELL_CAP];     // SELL: {val:hi32, col:lo32} at goff + j*32 + lane

// ---------------- fused prep: fillX + per-row count + weight fold ----------------
// y = (W0-W2-W4) x0 + W1 M1 + 2W2 M2' + W3 M3 + 2W4 M4'
#define NB_FILLX ((NV*CV)/256)           // 33792
#define NB_COUNT (2*NV)                  // 8192
#define NB_WPREP (((330*128+330*64)+255)/256) // 248
__global__ void k_prep(const float* __restrict__ inp, const float* __restrict__ hx,
                       const float* __restrict__ S0, const float* __restrict__ S1,
                       const float* __restrict__ W1, const float* __restrict__ W2) {
    int blk = blockIdx.x, t = threadIdx.x;
    if (blk < NB_FILLX) {
        int idx = blk * 256 + t;
        int n = idx / CV, col = idx - n * CV;
        int f = col >> 5, b = col & 31;
        float val;
        if (f < 2) { val = inp[(size_t)b * (NV * 2) + n * 2 + f]; g_X2[idx] = __float2half(val); }
        else         val = hx[(size_t)b * (NV * UV) + n * UV + (f - 2)];
        g_X1[idx] = __float2half(val);
    } else if (blk < NB_FILLX + NB_COUNT) {
        int b2 = blk - NB_FILLX;
        int s = b2 >> 12, row = b2 & (NV - 1);
        const float4* S = (const float4*)((s ? S1 : S0) + (size_t)row * NV) + t * 4;
        int cnt = 0;
        #pragma unroll
        for (int j = 0; j < 4; j++) {
            float4 v = S[j];
            cnt += (v.x != 0.0f) + (v.y != 0.0f) + (v.z != 0.0f) + (v.w != 0.0f);
        }
        __shared__ int sm[256];
        sm[t] = cnt; __syncthreads();
        for (int o = 128; o > 0; o >>= 1) { if (t < o) sm[t] += sm[t + o]; __syncthreads(); }
        if (t == 0) g_cnt[s][row] = sm[0];
    } else {
        int idx = (blk - NB_FILLX - NB_COUNT) * 256 + t;
        if (idx < 330 * 128) {
            int k = idx >> 7, m = k % 5;
            float v;
            if (m == 0)      v = W1[idx] - W1[idx + 2*128] - W1[idx + 4*128];
            else if (m == 2 || m == 4) v = 2.0f * W1[idx];
            else             v = W1[idx];
            g_W1p[idx] = v;
        } else if (idx < 330 * 128 + 330 * 64) {
            int j = idx - 330 * 128;
            int k = j >> 6, m = k % 5;
            float v;
            if (m == 0)      v = W2[j] - W2[j + 2*64] - W2[j + 4*64];
            else if (m == 2 || m == 4) v = 2.0f * W2[j];
            else             v = W2[j];
            g_W2p[j] = v;
        }
    }
}

// ---------------- group widths + offsets (grid 2, block 128) ----------------
__global__ void k_groups() {
    int s = blockIdx.x, g = threadIdx.x;
    int mx = 0;
    #pragma unroll 8
    for (int i = 0; i < 32; i++) mx = max(mx, g_cnt[s][g * 32 + i]);
    g_gw[s][g] = mx;
    __shared__ int sw[NG];
    int v = mx * 32;
    sw[g] = v; __syncthreads();
    for (int o = 1; o < NG; o <<= 1) {
        int y = (g >= o) ? sw[g - o] : 0;
        __syncthreads();
        sw[g] += y;
        __syncthreads();
    }
    g_goff[s][g] = sw[g] - v;
    if (g == NG - 1) g_goff[s][NG] = sw[g];
}

// ---------------- SELL fill (grid (4096,2), block 256) ----------------
__global__ void k_fill(const float* __restrict__ S0, const float* __restrict__ S1) {
    int row = blockIdx.x, s = blockIdx.y, t = threadIdx.x;
    const float* S = (s ? S1 : S0) + (size_t)row * NV;
    float4 va[4];
    #pragma unroll
    for (int j = 0; j < 4; j++) va[j] = ((const float4*)S)[t * 4 + j];
    const float* vf = (const float*)va;
    int cnt = 0;
    #pragma unroll
    for (int j = 0; j < 16; j++) cnt += (vf[j] != 0.0f);
    int lane = t & 31, w = t >> 5;
    int x = cnt;
    #pragma unroll
    for (int o = 1; o < 32; o <<= 1) { int y = __shfl_up_sync(~0u, x, o); if (lane >= o) x += y; }
    __shared__ int ws[8];
    if (lane == 31) ws[w] = x;
    __syncthreads();
    int woff = 0;
    for (int i = 0; i < w; i++) woff += ws[i];
    int g = row >> 5, rl = row & 31;
    int base = g_goff[s][g] + rl;
    int width = g_gw[s][g];
    int rank = woff + x - cnt;                    // exclusive rank within row
    #pragma unroll
    for (int j = 0; j < 16; j++) {
        float v = vf[j];
        if (v != 0.0f) {
            int dst = base + rank * 32;
            if (dst < SELL_CAP)
                g_ent[s][dst] = ((ull)(unsigned)__float_as_uint(v) << 32) | (unsigned)(t * 16 + j);
            rank++;
        }
    }
    int cr = g_cnt[s][row];
    for (int j = cr + t; j < width; j += 256) {   // pad with {0,0}
        int dst = base + j * 32;
        if (dst < SELL_CAP) g_ent[s][dst] = 0ull;
    }
}

// ---------------- SpMM core ----------------
// Tile: full-height 4096 x 8 fp16 stripe in smem; one row = 16 B = one LDS.128.
// Random rows spread over all 8 bank-quads via the row index's low bits.
__device__ __forceinline__ void load_tile(uint4* tq, const __half* __restrict__ X,
                                          int c0, int t) {
    #pragma unroll
    for (int k = 0; k < 4; k++) {
        int j = t + (k << 10);                       // row 0..4095
        tq[j] = *(const uint4*)(X + (size_t)j * CV + c0);
    }
}

__device__ __forceinline__ void accum(ull e, const uint4* tq, float* a) {
    unsigned c = (unsigned)e;
    float v = __uint_as_float((unsigned)(e >> 32));
    uint4 q = tq[c];
    float2 f0 = __half22float2(*reinterpret_cast<__half2*>(&q.x));
    float2 f1 = __half22float2(*reinterpret_cast<__half2*>(&q.y));
    float2 f2 = __half22float2(*reinterpret_cast<__half2*>(&q.z));
    float2 f3 = __half22float2(*reinterpret_cast<__half2*>(&q.w));
    a[0] += v * f0.x; a[1] += v * f0.y;
    a[2] += v * f1.x; a[3] += v * f1.y;
    a[4] += v * f2.x; a[5] += v * f2.y;
    a[6] += v * f3.x; a[7] += v * f3.y;
}

// SELL sweep: warp w handles groups w, w+32, w+64, w+96; lane = row within group.
__device__ __forceinline__ void sweep(const uint4* tq, const ull* __restrict__ ent,
                                      const int* __restrict__ goff, const int* __restrict__ gw,
                                      __half* __restrict__ Y, int c0, int t) {
    int lane = t & 31, w = t >> 5;
    #pragma unroll 1
    for (int g = w; g < NG; g += 32) {
        const ull* ep = ent + goff[g] + lane;
        int width = gw[g];
        float a[8];
        #pragma unroll
        for (int i = 0; i < 8; i++) a[i] = 0.0f;
        int j = 0;
        for (; j + 4 <= width; j += 4) {
            ull e0 = __ldg(ep + (j    ) * 32);
            ull e1 = __ldg(ep + (j + 1) * 32);
            ull e2 = __ldg(ep + (j + 2) * 32);
            ull e3 = __ldg(ep + (j + 3) * 32);
            accum(e0, tq, a); accum(e1, tq, a);
            accum(e2, tq, a); accum(e3, tq, a);
        }
        for (; j < width; j++) accum(__ldg(ep + j * 32), tq, a);
        int r = g * 32 + lane;
        __half2 h0 = __float22half2_rn(make_float2(a[0], a[1]));
        __half2 h1 = __float22half2_rn(make_float2(a[2], a[3]));
        __half2 h2 = __float22half2_rn(make_float2(a[4], a[5]));
        __half2 h3 = __float22half2_rn(make_float2(a[6], a[7]));
        uint4 o;
        o.x = *reinterpret_cast<unsigned*>(&h0);
        o.y = *reinterpret_cast<unsigned*>(&h1);
        o.z = *reinterpret_cast<unsigned*>(&h2);
        o.w = *reinterpret_cast<unsigned*>(&h3);
        *(uint4*)(Y + (size_t)r * CV + c0) = o;
    }
}

// first hop: M1 = S0 @ X, M3 = S1 @ X (one tile load serves both supports)
__global__ void __launch_bounds__(1024) k_spmmA(int which) {
    extern __shared__ uint4 tq[];
    int t = threadIdx.x, c0 = blockIdx.x * TW;
    load_tile(tq, which ? g_X2 : g_X1, c0, t);
    __syncthreads();
    sweep(tq, g_ent[0], g_goff[0], g_gw[0], g_M1, c0, t);
    sweep(tq, g_ent[1], g_goff[1], g_gw[1], g_M3, c0, t);
}

// second hop: M2 = S0 @ M1, M4 = S1 @ M3 (grid.y = support)
__global__ void __launch_bounds__(1024) k_spmmB() {
    extern __shared__ uint4 tq[];
    int t = threadIdx.x, c0 = blockIdx.x * TW, s = blockIdx.y;
    load_tile(tq, s ? g_M3 : g_M1, c0, t);
    __syncthreads();
    sweep(tq, g_ent[s], g_goff[s], g_gw[s], s ? g_M4 : g_M2, c0, t);
}

// ---------------- dense GEMM: (B*N, 330) @ (330, OUT), fused epilogues ----------------
// Weights read directly from device globals. Block: 4 n's x 32 b's = 128 rows. k = f*5+m.
// MODE 1: sigmoid; cols<64 -> r*hx (fp16) into g_X2 state slot; cols>=64 -> g_U.
// MODE 2: tanh; out = u*hx + (1-u)*c.
template<int OUT, int MODE>
__global__ void __launch_bounds__(256, 2) k_gemm(const float* __restrict__ bias,
                                                 const float* __restrict__ hx,
                                                 float* __restrict__ dout) {
    extern __shared__ float smem[];
    float* As = smem;                 // [66][128]
    float* Ws = smem + 66 * 128;      // [66][OUT]
    const float* __restrict__ W = (MODE == 1) ? g_W1p : g_W2p;
    const int t = threadIdx.x;
    const int n0 = blockIdx.x * 4;
    constexpr int CT = OUT / 8;
    constexpr int MR = OUT / 16;
    const int tr = t / CT, tc = t % CT;
    const int r0 = tr * MR, c0 = tc * 8;

    ull acc2[MR][4];
    #pragma unroll
    for (int r = 0; r < MR; r++)
        #pragma unroll
        for (int j = 0; j < 4; j++) acc2[r][j] = 0ull;

    #pragma unroll 1
    for (int m = 0; m < 5; m++) {
        const __half* Mm = (m == 0) ? (MODE == 1 ? g_X1 : g_X2)
                         : (m == 1) ? g_M1 : (m == 2) ? g_M2
                         : (m == 3) ? g_M3 : g_M4;
        for (int i = t; i < 66 * 64; i += 256) {     // 4224 half2 pairs = 66x128 floats
            int b2 = i & 15, r2 = i >> 4;
            int f = r2 % 66, nl = r2 / 66;
            float2 fv = __half22float2(*(const __half2*)(Mm + (size_t)(n0 + nl) * CV + f * 32 + b2 * 2));
            As[f * 128 + nl * 32 + b2 * 2]     = fv.x;
            As[f * 128 + nl * 32 + b2 * 2 + 1] = fv.y;
        }
        for (int i = t; i < 66 * OUT; i += 256) {
            int o = i % OUT, f = i / OUT;
            Ws[f * OUT + o] = W[(f * 5 + m) * OUT + o];
        }
        __syncthreads();
        #pragma unroll 2
        for (int f = 0; f < 66; f++) {
            ull w2[4];
            const ull* wp = (const ull*)(Ws + f * OUT + c0);
            #pragma unroll
            for (int j = 0; j < 4; j++) w2[j] = wp[j];
            const float* ap = As + f * 128 + r0;
            #pragma unroll
            for (int r = 0; r < MR; r++) {
                float a = ap[r];
                ull a2;
                asm("mov.b64 %0, {%1, %1};" : "=l"(a2) : "r"(__float_as_uint(a)));
                #pragma unroll
                for (int j = 0; j < 4; j++)
                    asm("fma.rn.f32x2 %0, %1, %2, %0;" : "+l"(acc2[r][j]) : "l"(a2), "l"(w2[j]));
            }
        }
        __syncthreads();
    }

    #pragma unroll
    for (int r = 0; r < MR; r++) {
        int row = r0 + r, nl = row >> 5, b = row & 31, n = n0 + nl;
        #pragma unroll
        for (int j = 0; j < 4; j++) {
            unsigned lo, hi;
            asm("mov.b64 {%0, %1}, %2;" : "=r"(lo), "=r"(hi) : "l"(acc2[r][j]));
            float v[2] = { __uint_as_float(lo), __uint_as_float(hi) };
            #pragma unroll
            for (int q = 0; q < 2; q++) {
                int o = c0 + j * 2 + q;
                float x = v[q] + bias[o];
                if (MODE == 1) {
                    float sg = 1.0f / (1.0f + expf(-x));
                    if (o < UV) {
                        float rh = sg * hx[(size_t)b * (NV * UV) + n * UV + o];
                        g_X2[(size_t)n * CV + (2 + o) * 32 + b] = __float2half(rh);
                    } else {
                        g_U[((size_t)b * NV + n) * UV + (o - UV)] = sg;
                    }
                } else {
                    float cv = tanhf(x);
                    float h = hx[(size_t)b * (NV * UV) + n * UV + o];
                    float u = g_U[((size_t)b * NV + n) * UV + o];
                    dout[(size_t)b * (NV * UV) + n * UV + o] = u * h + (1.0f - u) * cv;
                }
            }
        }
    }
}

// ---------------- launch ----------------
extern "C" void kernel_launch(void* const* d_in, const int* in_sizes, int n_in,
                              void* d_out, int out_size) {
    const float* inp = (const float*)d_in[0];
    const float* hx  = (const float*)d_in[1];
    const float* S0  = (const float*)d_in[2];
    const float* S1  = (const float*)d_in[3];
    const float* W1  = (const float*)d_in[4];
    const float* B1  = (const float*)d_in[5];
    const float* W2  = (const float*)d_in[6];
    const float* B2  = (const float*)d_in[7];
    float* out = (float*)d_out;

    const size_t tile_smem  = (size_t)NV * 16;                       // 65536 (fp16 tile)
    const size_t gemm1_smem = (66 * 128 + 66 * 128) * sizeof(float); // 67584
    const size_t gemm2_smem = (66 * 128 + 66 * 64) * sizeof(float);  // 50688
    cudaFuncSetAttribute(k_spmmA, cudaFuncAttributeMaxDynamicSharedMemorySize, (int)tile_smem);
    cudaFuncSetAttribute(k_spmmB, cudaFuncAttributeMaxDynamicSharedMemorySize, (int)tile_smem);
    cudaFuncSetAttribute(k_gemm<128,1>, cudaFuncAttributeMaxDynamicSharedMemorySize, (int)gemm1_smem);
    cudaFuncSetAttribute(k_gemm<64,2>,  cudaFuncAttributeMaxDynamicSharedMemorySize, (int)gemm2_smem);

    k_prep<<<NB_FILLX + NB_COUNT + NB_WPREP, 256>>>(inp, hx, S0, S1, W1, W2);
    k_groups<<<2, NG>>>();
    k_fill<<<dim3(NV, 2), 256>>>(S0, S1);

    // gconv 1 (state = hx)
    k_spmmA<<<NT, 1024, tile_smem>>>(0);
    k_spmmB<<<dim3(NT, 2), 1024, tile_smem>>>();
    k_gemm<128,1><<<NV / 4, 256, gemm1_smem>>>(B1, hx, out);

    // gconv 2 (state = r*hx, built by GEMM1 epilogue into g_X2)
    k_spmmA<<<NT, 1024, tile_smem>>>(1);
    k_spmmB<<<dim3(NT, 2), 1024, tile_smem>>>();
    k_gemm<64,2><<<NV / 4, 256, gemm2_smem>>>(B2, hx, out);
}

// round 8
// speedup vs baseline: 4.1173x; 1.0605x over previous
#include <cuda_runtime.h>
#include <cuda_fp16.h>
#include <stdint.h>
#include <math.h>

// DCGRU cell. N=4096, B=32, IN_DIM=2, U=64, K=2, 2 supports -> M=5, F=66, C=F*B=2112.
// Supports ~1% sparse -> on-device nnz-sorted SELL-32 + smem-tiled SpMM (fp16 tiles,
// fp32 accumulation). Chebyshev folded into weights. Dense GEMMs f32x2 FMA with fused
// sigmoid/tanh/GRU epilogues.

#define NV 4096
#define BV 32
#define FV 66
#define CV (FV*BV)        // 2112
#define UV 64
#define NG 128            // row groups of 32
#define SELL_CAP 420000
#define TW 8              // SpMM column-tile width
#define NT (CV/TW)        // 264 tiles

typedef unsigned long long ull;

// ---------------- device scratch ----------------
__device__ __align__(16) __half g_X1[(size_t)NV*CV];  // x0 for gconv1
__device__ __align__(16) __half g_X2[(size_t)NV*CV];  // x0 for gconv2 (inputs + r*hx)
__device__ __align__(16) __half g_M1[(size_t)NV*CV];  // S0 @ x0
__device__ __align__(16) __half g_M2[(size_t)NV*CV];  // S0 @ M1 (Chebyshev in weights)
__device__ __align__(16) __half g_M3[(size_t)NV*CV];  // S1 @ x0
__device__ __align__(16) __half g_M4[(size_t)NV*CV];  // S1 @ M3
__device__ float g_U [(size_t)BV*NV*UV];              // u gate (fp32)
__device__ float g_W1p[330*128];
__device__ float g_W2p[330*64];
__device__ int   g_cnt[2][NV];           // per-row nnz
__device__ int   g_rows[2][NV];          // slot -> row (nnz-descending)
__device__ int   g_slot[2][NV];          // row -> slot
__device__ int   g_gw [2][NG];           // per-group (32 slots) padded width
__device__ int   g_goff[2][NG+1];        // group entry offsets
__device__ ull   g_ent[2][SELL_CAP];     // SELL: {val:hi32, col:lo32} at goff + j*32 + lane

// ---------------- fused prep: fillX + per-row count + weight fold ----------------
// y = (W0-W2-W4) x0 + W1 M1 + 2W2 M2' + W3 M3 + 2W4 M4'
#define NB_FILLX ((NV*CV)/256)           // 33792
#define NB_COUNT (2*NV)                  // 8192
#define NB_WPREP (((330*128+330*64)+255)/256) // 248
__global__ void k_prep(const float* __restrict__ inp, const float* __restrict__ hx,
                       const float* __restrict__ S0, const float* __restrict__ S1,
                       const float* __restrict__ W1, const float* __restrict__ W2) {
    int blk = blockIdx.x, t = threadIdx.x;
    if (blk < NB_FILLX) {
        int idx = blk * 256 + t;
        int n = idx / CV, col = idx - n * CV;
        int f = col >> 5, b = col & 31;
        float val;
        if (f < 2) { val = inp[(size_t)b * (NV * 2) + n * 2 + f]; g_X2[idx] = __float2half(val); }
        else         val = hx[(size_t)b * (NV * UV) + n * UV + (f - 2)];
        g_X1[idx] = __float2half(val);
    } else if (blk < NB_FILLX + NB_COUNT) {
        int b2 = blk - NB_FILLX;
        int s = b2 >> 12, row = b2 & (NV - 1);
        const float4* S = (const float4*)((s ? S1 : S0) + (size_t)row * NV) + t * 4;
        int cnt = 0;
        #pragma unroll
        for (int j = 0; j < 4; j++) {
            float4 v = S[j];
            cnt += (v.x != 0.0f) + (v.y != 0.0f) + (v.z != 0.0f) + (v.w != 0.0f);
        }
        __shared__ int sm[256];
        sm[t] = cnt; __syncthreads();
        for (int o = 128; o > 0; o >>= 1) { if (t < o) sm[t] += sm[t + o]; __syncthreads(); }
        if (t == 0) g_cnt[s][row] = sm[0];
    } else {
        int idx = (blk - NB_FILLX - NB_COUNT) * 256 + t;
        if (idx < 330 * 128) {
            int k = idx >> 7, m = k % 5;
            float v;
            if (m == 0)      v = W1[idx] - W1[idx + 2*128] - W1[idx + 4*128];
            else if (m == 2 || m == 4) v = 2.0f * W1[idx];
            else             v = W1[idx];
            g_W1p[idx] = v;
        } else if (idx < 330 * 128 + 330 * 64) {
            int j = idx - 330 * 128;
            int k = j >> 6, m = k % 5;
            float v;
            if (m == 0)      v = W2[j] - W2[j + 2*64] - W2[j + 4*64];
            else if (m == 2 || m == 4) v = 2.0f * W2[j];
            else             v = W2[j];
            g_W2p[j] = v;
        }
    }
}

// ---------------- counting sort rows by nnz, descending (grid 2, block 1024) -------
// Equal-nnz placement uses atomics (order nondeterministic) but per-row SpMM results
// are independent of slot position, so the final output is deterministic.
__global__ void k_sort() {
    int s = blockIdx.x, t = threadIdx.x;
    __shared__ int hist[256], suf[256], off[256];
    if (t < 256) { hist[t] = 0; off[t] = 0; }
    __syncthreads();
    int c[4];
    #pragma unroll
    for (int i = 0; i < 4; i++) {
        int r = t * 4 + i;
        c[i] = min(g_cnt[s][r], 255);
        atomicAdd(&hist[c[i]], 1);
    }
    __syncthreads();
    if (t < 256) suf[t] = hist[t];
    __syncthreads();
    for (int o = 1; o < 256; o <<= 1) {          // inclusive suffix scan
        int v = 0;
        if (t < 256 && t + o < 256) v = suf[t + o];
        __syncthreads();
        if (t < 256) suf[t] += v;
        __syncthreads();
    }
    #pragma unroll
    for (int i = 0; i < 4; i++) {
        int r = t * 4 + i;
        int base = suf[c[i]] - hist[c[i]];       // rows with strictly larger nnz
        int pos = base + atomicAdd(&off[c[i]], 1);
        g_rows[s][pos] = r;
        g_slot[s][r] = pos;
    }
}

// ---------------- group widths + offsets (grid 2, block 128) ----------------
__global__ void k_groups() {
    int s = blockIdx.x, g = threadIdx.x;
    int mx = 0;
    #pragma unroll 8
    for (int i = 0; i < 32; i++) mx = max(mx, g_cnt[s][g_rows[s][g * 32 + i]]);
    g_gw[s][g] = mx;
    __shared__ int sw[NG];
    int v = mx * 32;
    sw[g] = v; __syncthreads();
    for (int o = 1; o < NG; o <<= 1) {
        int y = (g >= o) ? sw[g - o] : 0;
        __syncthreads();
        sw[g] += y;
        __syncthreads();
    }
    g_goff[s][g] = sw[g] - v;
    if (g == NG - 1) g_goff[s][NG] = sw[g];
}

// ---------------- SELL fill (grid (4096,2), block 256) ----------------
__global__ void k_fill(const float* __restrict__ S0, const float* __restrict__ S1) {
    int row = blockIdx.x, s = blockIdx.y, t = threadIdx.x;
    const float* S = (s ? S1 : S0) + (size_t)row * NV;
    float4 va[4];
    #pragma unroll
    for (int j = 0; j < 4; j++) va[j] = ((const float4*)S)[t * 4 + j];
    const float* vf = (const float*)va;
    int cnt = 0;
    #pragma unroll
    for (int j = 0; j < 16; j++) cnt += (vf[j] != 0.0f);
    int lane = t & 31, w = t >> 5;
    int x = cnt;
    #pragma unroll
    for (int o = 1; o < 32; o <<= 1) { int y = __shfl_up_sync(~0u, x, o); if (lane >= o) x += y; }
    __shared__ int ws[8];
    if (lane == 31) ws[w] = x;
    __syncthreads();
    int woff = 0;
    for (int i = 0; i < w; i++) woff += ws[i];
    int slot = g_slot[s][row];
    int g = slot >> 5, sl = slot & 31;
    int base = g_goff[s][g] + sl;
    int width = g_gw[s][g];
    int rank = woff + x - cnt;                    // exclusive rank within row
    #pragma unroll
    for (int j = 0; j < 16; j++) {
        float v = vf[j];
        if (v != 0.0f) {
            int dst = base + rank * 32;
            if (dst < SELL_CAP)
                g_ent[s][dst] = ((ull)(unsigned)__float_as_uint(v) << 32) | (unsigned)(t * 16 + j);
            rank++;
        }
    }
    int cr = g_cnt[s][row];
    for (int j = cr + t; j < width; j += 256) {   // pad with {0,0}
        int dst = base + j * 32;
        if (dst < SELL_CAP) g_ent[s][dst] = 0ull;
    }
}

// ---------------- SpMM core ----------------
// Tile: full-height 4096 x 8 fp16 stripe in smem; one row = 16 B = one LDS.128.
__device__ __forceinline__ void load_tile(uint4* tq, const __half* __restrict__ X,
                                          int c0, int t) {
    #pragma unroll
    for (int k = 0; k < 8; k++) {
        int j = t + (k << 9);                        // row 0..4095 (512 threads)
        tq[j] = *(const uint4*)(X + (size_t)j * CV + c0);
    }
}

__device__ __forceinline__ void accum(ull e, const uint4* tq, float* a) {
    unsigned c = (unsigned)e;
    float v = __uint_as_float((unsigned)(e >> 32));
    uint4 q = tq[c];
    float2 f0 = __half22float2(*reinterpret_cast<__half2*>(&q.x));
    float2 f1 = __half22float2(*reinterpret_cast<__half2*>(&q.y));
    float2 f2 = __half22float2(*reinterpret_cast<__half2*>(&q.z));
    float2 f3 = __half22float2(*reinterpret_cast<__half2*>(&q.w));
    a[0] += v * f0.x; a[1] += v * f0.y;
    a[2] += v * f1.x; a[3] += v * f1.y;
    a[4] += v * f2.x; a[5] += v * f2.y;
    a[6] += v * f3.x; a[7] += v * f3.y;
}

// SELL sweep (512 threads = 16 warps): warp w handles groups w, w+16, ...;
// lane = slot within group; output row via g_rows.
__device__ __forceinline__ void sweep(const uint4* tq, const ull* __restrict__ ent,
                                      const int* __restrict__ goff, const int* __restrict__ gw,
                                      const int* __restrict__ rows,
                                      __half* __restrict__ Y, int c0, int t) {
    int lane = t & 31, w = t >> 5;
    #pragma unroll 1
    for (int g = w; g < NG; g += 16) {
        const ull* ep = ent + goff[g] + lane;
        int width = gw[g];
        float a[8];
        #pragma unroll
        for (int i = 0; i < 8; i++) a[i] = 0.0f;
        int j = 0;
        for (; j + 4 <= width; j += 4) {
            ull e0 = __ldg(ep + (j    ) * 32);
            ull e1 = __ldg(ep + (j + 1) * 32);
            ull e2 = __ldg(ep + (j + 2) * 32);
            ull e3 = __ldg(ep + (j + 3) * 32);
            accum(e0, tq, a); accum(e1, tq, a);
            accum(e2, tq, a); accum(e3, tq, a);
        }
        for (; j < width; j++) accum(__ldg(ep + j * 32), tq, a);
        int r = __ldg(rows + g * 32 + lane);
        __half2 h0 = __float22half2_rn(make_float2(a[0], a[1]));
        __half2 h1 = __float22half2_rn(make_float2(a[2], a[3]));
        __half2 h2 = __float22half2_rn(make_float2(a[4], a[5]));
        __half2 h3 = __float22half2_rn(make_float2(a[6], a[7]));
        uint4 o;
        o.x = *reinterpret_cast<unsigned*>(&h0);
        o.y = *reinterpret_cast<unsigned*>(&h1);
        o.z = *reinterpret_cast<unsigned*>(&h2);
        o.w = *reinterpret_cast<unsigned*>(&h3);
        *(uint4*)(Y + (size_t)r * CV + c0) = o;
    }
}

// first hop: M1 = S0 @ X, M3 = S1 @ X (one tile load serves both supports)
__global__ void __launch_bounds__(512) k_spmmA(int which) {
    extern __shared__ uint4 tq[];
    int t = threadIdx.x, c0 = blockIdx.x * TW;
    load_tile(tq, which ? g_X2 : g_X1, c0, t);
    __syncthreads();
    sweep(tq, g_ent[0], g_goff[0], g_gw[0], g_rows[0], g_M1, c0, t);
    sweep(tq, g_ent[1], g_goff[1], g_gw[1], g_rows[1], g_M3, c0, t);
}

// second hop: M2 = S0 @ M1, then M4 = S1 @ M3 (same CTA, tile reloaded)
__global__ void __launch_bounds__(512) k_spmmB() {
    extern __shared__ uint4 tq[];
    int t = threadIdx.x, c0 = blockIdx.x * TW;
    load_tile(tq, g_M1, c0, t);
    __syncthreads();
    sweep(tq, g_ent[0], g_goff[0], g_gw[0], g_rows[0], g_M2, c0, t);
    __syncthreads();
    load_tile(tq, g_M3, c0, t);
    __syncthreads();
    sweep(tq, g_ent[1], g_goff[1], g_gw[1], g_rows[1], g_M4, c0, t);
}

// ---------------- dense GEMM: (B*N, 330) @ (330, OUT), fused epilogues ----------------
// Weights read directly from device globals. Block: 4 n's x 32 b's = 128 rows. k = f*5+m.
// MODE 1: sigmoid; cols<64 -> r*hx (fp16) into g_X2 state slot; cols>=64 -> g_U.
// MODE 2: tanh; out = u*hx + (1-u)*c.
template<int OUT, int MODE>
__global__ void __launch_bounds__(256, 2) k_gemm(const float* __restrict__ bias,
                                                 const float* __restrict__ hx,
                                                 float* __restrict__ dout) {
    extern __shared__ float smem[];
    float* As = smem;                 // [66][128]
    float* Ws = smem + 66 * 128;      // [66][OUT]
    const float* __restrict__ W = (MODE == 1) ? g_W1p : g_W2p;
    const int t = threadIdx.x;
    const int n0 = blockIdx.x * 4;
    constexpr int CT = OUT / 8;
    constexpr int MR = OUT / 16;
    const int tr = t / CT, tc = t % CT;
    const int r0 = tr * MR, c0 = tc * 8;

    ull acc2[MR][4];
    #pragma unroll
    for (int r = 0; r < MR; r++)
        #pragma unroll
        for (int j = 0; j < 4; j++) acc2[r][j] = 0ull;

    #pragma unroll 1
    for (int m = 0; m < 5; m++) {
        const __half* Mm = (m == 0) ? (MODE == 1 ? g_X1 : g_X2)
                         : (m == 1) ? g_M1 : (m == 2) ? g_M2
                         : (m == 3) ? g_M3 : g_M4;
        for (int i = t; i < 66 * 64; i += 256) {     // 4224 half2 pairs = 66x128 floats
            int b2 = i & 15, r2 = i >> 4;
            int f = r2 % 66, nl = r2 / 66;
            float2 fv = __half22float2(*(const __half2*)(Mm + (size_t)(n0 + nl) * CV + f * 32 + b2 * 2));
            As[f * 128 + nl * 32 + b2 * 2]     = fv.x;
            As[f * 128 + nl * 32 + b2 * 2 + 1] = fv.y;
        }
        for (int i = t; i < 66 * OUT; i += 256) {
            int o = i % OUT, f = i / OUT;
            Ws[f * OUT + o] = W[(f * 5 + m) * OUT + o];
        }
        __syncthreads();
        #pragma unroll 2
        for (int f = 0; f < 66; f++) {
            ull w2[4];
            const ull* wp = (const ull*)(Ws + f * OUT + c0);
            #pragma unroll
            for (int j = 0; j < 4; j++) w2[j] = wp[j];
            const float* ap = As + f * 128 + r0;
            #pragma unroll
            for (int r = 0; r < MR; r++) {
                float a = ap[r];
                ull a2;
                asm("mov.b64 %0, {%1, %1};" : "=l"(a2) : "r"(__float_as_uint(a)));
                #pragma unroll
                for (int j = 0; j < 4; j++)
                    asm("fma.rn.f32x2 %0, %1, %2, %0;" : "+l"(acc2[r][j]) : "l"(a2), "l"(w2[j]));
            }
        }
        __syncthreads();
    }

    #pragma unroll
    for (int r = 0; r < MR; r++) {
        int row = r0 + r, nl = row >> 5, b = row & 31, n = n0 + nl;
        #pragma unroll
        for (int j = 0; j < 4; j++) {
            unsigned lo, hi;
            asm("mov.b64 {%0, %1}, %2;" : "=r"(lo), "=r"(hi) : "l"(acc2[r][j]));
            float v[2] = { __uint_as_float(lo), __uint_as_float(hi) };
            #pragma unroll
            for (int q = 0; q < 2; q++) {
                int o = c0 + j * 2 + q;
                float x = v[q] + bias[o];
                if (MODE == 1) {
                    float sg = 1.0f / (1.0f + expf(-x));
                    if (o < UV) {
                        float rh = sg * hx[(size_t)b * (NV * UV) + n * UV + o];
                        g_X2[(size_t)n * CV + (2 + o) * 32 + b] = __float2half(rh);
                    } else {
                        g_U[((size_t)b * NV + n) * UV + (o - UV)] = sg;
                    }
                } else {
                    float cv = tanhf(x);
                    float h = hx[(size_t)b * (NV * UV) + n * UV + o];
                    float u = g_U[((size_t)b * NV + n) * UV + o];
                    dout[(size_t)b * (NV * UV) + n * UV + o] = u * h + (1.0f - u) * cv;
                }
            }
        }
    }
}

// ---------------- launch ----------------
extern "C" void kernel_launch(void* const* d_in, const int* in_sizes, int n_in,
                              void* d_out, int out_size) {
    const float* inp = (const float*)d_in[0];
    const float* hx  = (const float*)d_in[1];
    const float* S0  = (const float*)d_in[2];
    const float* S1  = (const float*)d_in[3];
    const float* W1  = (const float*)d_in[4];
    const float* B1  = (const float*)d_in[5];
    const float* W2  = (const float*)d_in[6];
    const float* B2  = (const float*)d_in[7];
    float* out = (float*)d_out;

    const size_t tile_smem  = (size_t)NV * 16;                       // 65536 (fp16 tile)
    const size_t gemm1_smem = (66 * 128 + 66 * 128) * sizeof(float); // 67584
    const size_t gemm2_smem = (66 * 128 + 66 * 64) * sizeof(float);  // 50688
    cudaFuncSetAttribute(k_spmmA, cudaFuncAttributeMaxDynamicSharedMemorySize, (int)tile_smem);
    cudaFuncSetAttribute(k_spmmB, cudaFuncAttributeMaxDynamicSharedMemorySize, (int)tile_smem);
    cudaFuncSetAttribute(k_gemm<128,1>, cudaFuncAttributeMaxDynamicSharedMemorySize, (int)gemm1_smem);
    cudaFuncSetAttribute(k_gemm<64,2>,  cudaFuncAttributeMaxDynamicSharedMemorySize, (int)gemm2_smem);

    k_prep<<<NB_FILLX + NB_COUNT + NB_WPREP, 256>>>(inp, hx, S0, S1, W1, W2);
    k_sort<<<2, 1024>>>();
    k_groups<<<2, NG>>>();
    k_fill<<<dim3(NV, 2), 256>>>(S0, S1);

    // gconv 1 (state = hx)
    k_spmmA<<<NT, 512, tile_smem>>>(0);
    k_spmmB<<<NT, 512, tile_smem>>>();
    k_gemm<128,1><<<NV / 4, 256, gemm1_smem>>>(B1, hx, out);

    // gconv 2 (state = r*hx, built by GEMM1 epilogue into g_X2)
    k_spmmA<<<NT, 512, tile_smem>>>(1);
    k_spmmB<<<NT, 512, tile_smem>>>();
    k_gemm<64,2><<<NV / 4, 256, gemm2_smem>>>(B2, hx, out);
}